// round 15
// baseline (speedup 1.0000x reference)
#include <cuda_runtime.h>
#include <cstdint>

#define B_   4
#define N_   2000
#define M_   2000
#define R_   8000      // B*N rows
#define K_   16
#define EMB_ 128
#define E2_  256
#define PENALTY_ (-10.0f)
#define EPS_ 1e-5f
#define TAU_ 0.02f
#define CAP_ 128       // E[C]=40, sd 6.2
#define SLOT_ 8        // per-lane idx slots; overflow -> exact fallback
#define RPB_ 8         // rows per block
#define GA_  (R_ / RPB_)   // 1000
#define BPB_ (GA_ / B_)    // 250
#define SCH_ 8

typedef unsigned long long ull;

// ---- packed f32x2 helpers ----
__device__ __forceinline__ ull fma2(ull a, ull b, ull c) {
  ull d;
  asm("fma.rn.f32x2 %0, %1, %2, %3;" : "=l"(d) : "l"(a), "l"(b), "l"(c));
  return d;
}
__device__ __forceinline__ ull add2(ull a, ull b) {
  ull d;
  asm("add.rn.f32x2 %0, %1, %2;" : "=l"(d) : "l"(a), "l"(b));
  return d;
}
__device__ __forceinline__ ull packdup(float x) {
  ull r;
  asm("mov.b64 %0, {%1, %1};" : "=l"(r) : "f"(x));
  return r;
}
__device__ __forceinline__ void unpack2(ull v, float& x, float& y) {
  asm("mov.b64 {%0, %1}, %2;" : "=f"(x), "=f"(y) : "l"(v));
}

// ---- scratch ----
__device__ __align__(16) float g_W1t[34 * 128];
__device__ __align__(16) float g_W2t[128 * 256];
__device__ __align__(16) float g_W3t[256 * 128];
__device__ __align__(16) float g_W4t[128 * 16];
__device__ __align__(16) float g_h2[(size_t)R_ * E2_];
__device__ float g_sd[R_ * K_];
__device__ int   g_si[R_ * K_];
__device__ float g_psA [GA_ * E2_];
__device__ float g_pssA[GA_ * E2_];
__device__ float g_ps [B_ * SCH_ * E2_];
__device__ float g_pss[B_ * SCH_ * E2_];
__device__ float g_scale[B_ * E2_];
__device__ float g_shift[B_ * E2_];
__device__ int   g_bcnt;

// ---- kernel T: all four weight transposes ----
__global__ __launch_bounds__(256) void kT(const float* __restrict__ W1,
                                          const float* __restrict__ W2,
                                          const float* __restrict__ W3,
                                          const float* __restrict__ W4) {
  int t = blockIdx.x * blockDim.x + threadIdx.x;
  int stride = gridDim.x * blockDim.x;
  for (int o = t; o < 34 * 128; o += stride) { int co = o & 127, j = o >> 7; g_W1t[o] = W1[co * 34 + j]; }
  for (int o = t; o < 128 * 256; o += stride) { int co = o & 255, c = o >> 8; g_W2t[o] = W2[co * 128 + c]; }
  for (int o = t; o < 256 * 128; o += stride) { int co = o & 127, c = o >> 7; g_W3t[o] = W3[co * 256 + c]; }
  for (int o = t; o < 128 * 16;  o += stride) { int k  = o & 15,  c = o >> 4; g_W4t[o] = W4[k * 128 + c]; }
}

// ---- kernel A: top-16 (all warps), then warps 0-3 MLP || warps 4-7 fill ----
__global__ __launch_bounds__(256) void kA(const float* __restrict__ theta,
                                          const float* __restrict__ dist,
                                          const float* __restrict__ insf,
                                          const float* __restrict__ b1,
                                          const float* __restrict__ b2,
                                          float* __restrict__ out) {
  int blk = blockIdx.x;
  int r0 = blk * RPB_;
  int tid = threadIdx.x, wid = tid >> 5, lane = tid & 31;

  __shared__ int slots[RPB_][32][SLOT_];           // 8KB
  __shared__ ull cand[RPB_][CAP_];                 // 8KB
  __shared__ float sds[RPB_][K_];
  __shared__ int   sis[RPB_][K_];
  __shared__ float xs[RPB_][34];
  __shared__ __align__(16) float h1t[128][RPB_];   // 4KB

  // ---- filter pass 1: read-only streaming scan (warp wid owns row r0+wid) ----
  int r = r0 + wid;
  const float* drow = dist + (size_t)r * M_;
  const float4* drow4 = reinterpret_cast<const float4*>(drow);
  int ci = 0;
  #pragma unroll 4
  for (int it = 0; it < 16; it++) {
    int i4 = it * 32 + lane;
    float4 v = (i4 < M_ / 4) ? drow4[i4] : make_float4(1.f, 1.f, 1.f, 1.f);
    int base = i4 * 4;
    if (v.x < TAU_) { if (ci < SLOT_) slots[wid][lane][ci] = base + 0; ci++; }
    if (v.y < TAU_) { if (ci < SLOT_) slots[wid][lane][ci] = base + 1; ci++; }
    if (v.z < TAU_) { if (ci < SLOT_) slots[wid][lane][ci] = base + 2; ci++; }
    if (v.w < TAU_) { if (ci < SLOT_) slots[wid][lane][ci] = base + 3; ci++; }
  }
  unsigned om = __ballot_sync(0xffffffffu, ci > SLOT_);
  int pre = ci;
  #pragma unroll
  for (int d = 1; d < 32; d <<= 1) {
    int o = __shfl_up_sync(0xffffffffu, pre, d);
    if (lane >= d) pre += o;
  }
  int C = __shfl_sync(0xffffffffu, pre, 31);
  int p = pre - ci;

  if (om == 0 && C >= K_ && C <= CAP_) {
    // ---- compaction + rank-select ----
    for (int s = 0; s < ci; s++) {
      int idx = slots[wid][lane][s];
      float v = __ldg(&drow[idx]);
      cand[wid][p + s] = (((ull)__float_as_uint(v)) << 32) | (unsigned)idx;
    }
    __syncwarp();
    for (int i = lane; i < C; i += 32) {
      ull key = cand[wid][i];
      int rank = 0;
      for (int j = 0; j < C; j++) rank += (cand[wid][j] < key);
      if (rank < K_) {
        sds[wid][rank] = __uint_as_float((unsigned)(key >> 32));
        sis[wid][rank] = (int)(unsigned)(key & 0xffffffffu);
      }
    }
  } else {
    // ---- exact fallback (deterministic, rare) ----
    ull last = 0ULL;
    for (int k = 0; k < K_; k++) {
      ull m = ~0ULL;
      for (int i = lane; i < M_; i += 32) {
        ull c = (((ull)__float_as_uint(drow[i])) << 32) | (unsigned)i;
        if ((k == 0 || c > last) && c < m) m = c;
      }
      #pragma unroll
      for (int off = 16; off; off >>= 1) {
        ull o = __shfl_down_sync(0xffffffffu, m, off);
        m = (o < m) ? o : m;
      }
      m = __shfl_sync(0xffffffffu, m, 0);
      if (lane == 0) {
        sds[wid][k] = __uint_as_float((unsigned)(m >> 32));
        sis[wid][k] = (int)(unsigned)(m & 0xffffffffu);
      }
      last = m;
    }
  }
  __syncwarp();

  // ---- build x per row ----
  if (lane < K_) {
    float maxd = sds[wid][K_ - 1];
    float nd = sds[wid][lane] / maxd;
    xs[wid][lane] = nd;
    xs[wid][K_ + lane] = theta[(size_t)r * M_ + sis[wid][lane]];
    g_sd[r * K_ + lane] = nd;
    g_si[r * K_ + lane] = sis[wid][lane];
  }
  if (lane == 16) xs[wid][32] = insf[r];
  if (lane == 17) xs[wid][33] = insf[R_ + r];
  __syncthreads();

  if (tid < 128) {
    // ======== warps 0-3: MLP for all 8 rows ========
    // ---- layer 1: 34 -> 128; thread co computes all 8 rows ----
    {
      int co = tid;
      float bb = b1[co];
      float a[RPB_];
      #pragma unroll
      for (int rr = 0; rr < RPB_; rr++) a[rr] = bb;
      #pragma unroll
      for (int j = 0; j < 34; j++) {
        float w = g_W1t[j * 128 + co];
        #pragma unroll
        for (int rr = 0; rr < RPB_; rr++) a[rr] = fmaf(xs[rr][j], w, a[rr]);
      }
      #pragma unroll
      for (int rr = 0; rr < RPB_; rr++) h1t[co][rr] = fmaxf(a[rr], 0.f);
    }
    asm volatile("bar.sync 1, 128;" ::: "memory");   // warps 0-3 only

    // ---- layer 2: 128 -> 256; thread pr owns one output-pair, full c-loop ----
    {
      int pr = tid;
      const ull* W2p = reinterpret_cast<const ull*>(g_W2t);
      ull acc[RPB_];
      #pragma unroll
      for (int rr = 0; rr < RPB_; rr++) acc[rr] = 0ULL;
      #pragma unroll 8
      for (int c = 0; c < 128; c++) {
        ull w = W2p[c * 128 + pr];
        float4 ha = *reinterpret_cast<const float4*>(&h1t[c][0]);
        float4 hb = *reinterpret_cast<const float4*>(&h1t[c][4]);
        acc[0] = fma2(packdup(ha.x), w, acc[0]);
        acc[1] = fma2(packdup(ha.y), w, acc[1]);
        acc[2] = fma2(packdup(ha.z), w, acc[2]);
        acc[3] = fma2(packdup(ha.w), w, acc[3]);
        acc[4] = fma2(packdup(hb.x), w, acc[4]);
        acc[5] = fma2(packdup(hb.y), w, acc[5]);
        acc[6] = fma2(packdup(hb.z), w, acc[6]);
        acc[7] = fma2(packdup(hb.w), w, acc[7]);
      }
      // ---- epilogue straight from registers: bias+relu, h2, norm partials ----
      float2 bb = reinterpret_cast<const float2*>(b2)[pr];
      float s0 = 0.f, s1 = 0.f, q0 = 0.f, q1 = 0.f;
      #pragma unroll
      for (int rr = 0; rr < RPB_; rr++) {
        float sx, sy;
        unpack2(acc[rr], sx, sy);
        float2 o;
        o.x = fmaxf(sx + bb.x, 0.f);
        o.y = fmaxf(sy + bb.y, 0.f);
        reinterpret_cast<float2*>(g_h2)[(size_t)(r0 + rr) * 128 + pr] = o;
        s0 += o.x; q0 = fmaf(o.x, o.x, q0);
        s1 += o.y; q1 = fmaf(o.y, o.y, q1);
      }
      g_psA [blk * E2_ + 2 * pr + 0] = s0;
      g_psA [blk * E2_ + 2 * pr + 1] = s1;
      g_pssA[blk * E2_ + 2 * pr + 0] = q0;
      g_pssA[blk * E2_ + 2 * pr + 1] = q1;
    }
  } else {
    // ======== warps 4-7: PENALTY fill (overlaps MLP issue on other warps) ====
    float4* o4 = reinterpret_cast<float4*>(out + (size_t)r0 * M_);
    float4 pen = make_float4(PENALTY_, PENALTY_, PENALTY_, PENALTY_);
    for (int i = tid - 128; i < RPB_ * M_ / 4; i += 128) o4[i] = pen;
  }
}

// ---- kernel B ----
__global__ __launch_bounds__(256) void kB(const float* __restrict__ gamma,
                                          const float* __restrict__ beta) {
  int blk = blockIdx.x;
  int b = blk >> 3, s = blk & 7;
  int t = threadIdx.x;
  int i0 = s * 32, i1 = min(i0 + 32, BPB_);
  float sum = 0.f, sq = 0.f;
  for (int i = i0; i < i1; i++) {
    int pb = b * BPB_ + i;
    sum += g_psA [pb * E2_ + t];
    sq  += g_pssA[pb * E2_ + t];
  }
  g_ps [(b * SCH_ + s) * E2_ + t] = sum;
  g_pss[(b * SCH_ + s) * E2_ + t] = sq;

  __threadfence();
  __shared__ int isLast;
  if (t == 0) isLast = (atomicAdd(&g_bcnt, 1) == B_ * SCH_ - 1) ? 1 : 0;
  __syncthreads();
  if (!isLast) return;
  if (t == 0) g_bcnt = 0;

  for (int bb = 0; bb < B_; bb++) {
    float sf = 0.f, ssf = 0.f;
    #pragma unroll
    for (int c2 = 0; c2 < SCH_; c2++) {
      sf  += g_ps [(bb * SCH_ + c2) * E2_ + t];
      ssf += g_pss[(bb * SCH_ + c2) * E2_ + t];
    }
    float mean = sf * (1.f / N_);
    float var  = ssf * (1.f / N_) - mean * mean;
    float inv  = rsqrtf(var + EPS_);
    float sc = inv * gamma[t];
    g_scale[bb * E2_ + t] = sc;
    g_shift[bb * E2_ + t] = beta[t] - mean * sc;
  }
}

// ---- kernel C: 8 rows/block; norm, layers 3-4, scatter (no fill) ----
__global__ __launch_bounds__(256, 6) void kC(const float* __restrict__ b3,
                                             const float* __restrict__ b4,
                                             float* __restrict__ out) {
  int r0 = blockIdx.x * RPB_;
  int tid = threadIdx.x;
  int b = r0 / N_;

  __shared__ __align__(16) float hn[E2_][RPB_];    // 8KB
  __shared__ ull p3[RPB_][4][64];                  // 16KB, lane-consecutive
  __shared__ __align__(16) float h3t[EMB_][RPB_];  // 4KB
  __shared__ float part[2][128];

  // ---- load h2 + instance-norm ----
  {
    float sc = g_scale[b * E2_ + tid];
    float sh = g_shift[b * E2_ + tid];
    #pragma unroll
    for (int rr = 0; rr < RPB_; rr++) {
      float v = g_h2[(size_t)(r0 + rr) * E2_ + tid];
      hn[tid][rr] = fmaf(v, sc, sh);
    }
  }
  __syncthreads();

  // ---- layer 3: 256 -> 128 for 8 rows ----
  {
    int pr = tid & 63, seg = tid >> 6;
    int c0 = seg * 64;
    const ull* W3p = reinterpret_cast<const ull*>(g_W3t);
    ull acc[RPB_];
    #pragma unroll
    for (int rr = 0; rr < RPB_; rr++) acc[rr] = 0ULL;
    #pragma unroll 8
    for (int cc = 0; cc < 64; cc++) {
      int c = c0 + cc;
      ull w = W3p[c * 64 + pr];
      float4 ha = *reinterpret_cast<const float4*>(&hn[c][0]);
      float4 hb = *reinterpret_cast<const float4*>(&hn[c][4]);
      acc[0] = fma2(packdup(ha.x), w, acc[0]);
      acc[1] = fma2(packdup(ha.y), w, acc[1]);
      acc[2] = fma2(packdup(ha.z), w, acc[2]);
      acc[3] = fma2(packdup(ha.w), w, acc[3]);
      acc[4] = fma2(packdup(hb.x), w, acc[4]);
      acc[5] = fma2(packdup(hb.y), w, acc[5]);
      acc[6] = fma2(packdup(hb.z), w, acc[6]);
      acc[7] = fma2(packdup(hb.w), w, acc[7]);
    }
    #pragma unroll
    for (int rr = 0; rr < RPB_; rr++) p3[rr][seg][pr] = acc[rr];
  }
  __syncthreads();
  // ---- combine -> h3t, all 256 threads (2 rows each) ----
  {
    int pr = tid & 63, g = tid >> 6;
    float2 bb = reinterpret_cast<const float2*>(b3)[pr];
    #pragma unroll
    for (int q = 0; q < 2; q++) {
      int rr = 2 * g + q;
      ull s = add2(add2(p3[rr][0][pr], p3[rr][1][pr]),
                   add2(p3[rr][2][pr], p3[rr][3][pr]));
      float sx, sy;
      unpack2(s, sx, sy);
      h3t[2 * pr + 0][rr] = fmaxf(sx + bb.x, 0.f);
      h3t[2 * pr + 1][rr] = fmaxf(sy + bb.y, 0.f);
    }
  }
  __syncthreads();

  // ---- layer 4: 128 -> 16 per row (2 c-segments of 64) ----
  {
    int rk = tid & 127, seg = tid >> 7;
    int row = rk >> 4, k = rk & 15;
    int c0 = seg * 64;
    float acc = 0.f;
    #pragma unroll 8
    for (int cc = 0; cc < 64; cc++) {
      int c = c0 + cc;
      acc = fmaf(h3t[c][row], g_W4t[c * 16 + k], acc);
    }
    part[seg][rk] = acc;
  }
  __syncthreads();

  // ---- combine, subtract sorted_dist, scatter ----
  if (tid < 128) {
    int row = tid >> 4, k = tid & 15;
    int r = r0 + row;
    float val = part[0][tid] + part[1][tid] + b4[k] - g_sd[r * K_ + k];
    int idx = g_si[r * K_ + k];
    out[(size_t)r * M_ + idx] = val;
  }
}

extern "C" void kernel_launch(void* const* d_in, const int* in_sizes, int n_in,
                              void* d_out, int out_size) {
  const float* theta = (const float*)d_in[0];
  const float* dist  = (const float*)d_in[1];
  const float* insf  = (const float*)d_in[2];
  const float* W1    = (const float*)d_in[3];
  const float* b1    = (const float*)d_in[4];
  const float* W2    = (const float*)d_in[5];
  const float* b2    = (const float*)d_in[6];
  const float* W3    = (const float*)d_in[7];
  const float* b3    = (const float*)d_in[8];
  const float* W4    = (const float*)d_in[9];
  const float* b4    = (const float*)d_in[10];
  const float* gamma = (const float*)d_in[11];
  const float* beta  = (const float*)d_in[12];
  float* out = (float*)d_out;

  kT<<<72, 256>>>(W1, W2, W3, W4);
  kA<<<GA_, 256>>>(theta, dist, insf, b1, b2, out);
  kB<<<B_ * SCH_, 256>>>(gamma, beta);
  kC<<<GA_, 256>>>(b3, b4, out);
}

// round 16
// speedup vs baseline: 1.1817x; 1.1817x over previous
#include <cuda_runtime.h>
#include <cstdint>

#define B_   4
#define N_   2000
#define M_   2000
#define R_   8000      // B*N rows
#define K_   16
#define EMB_ 128
#define E2_  256
#define PENALTY_ (-10.0f)
#define EPS_ 1e-5f
#define TAU_ 0.02f
#define CAP_ 128       // E[C]=40, sd 6.2
#define SLOT_ 8        // per-lane idx slots; overflow -> exact fallback
#define RPB_ 8         // rows per block
#define GA_  (R_ / RPB_)   // 1000
#define BPB_ (GA_ / B_)    // 250
#define SCH_ 8

typedef unsigned long long ull;

// ---- packed f32x2 helpers ----
__device__ __forceinline__ ull fma2(ull a, ull b, ull c) {
  ull d;
  asm("fma.rn.f32x2 %0, %1, %2, %3;" : "=l"(d) : "l"(a), "l"(b), "l"(c));
  return d;
}
__device__ __forceinline__ ull add2(ull a, ull b) {
  ull d;
  asm("add.rn.f32x2 %0, %1, %2;" : "=l"(d) : "l"(a), "l"(b));
  return d;
}
__device__ __forceinline__ ull packdup(float x) {
  ull r;
  asm("mov.b64 %0, {%1, %1};" : "=l"(r) : "f"(x));
  return r;
}
__device__ __forceinline__ void unpack2(ull v, float& x, float& y) {
  asm("mov.b64 {%0, %1}, %2;" : "=f"(x), "=f"(y) : "l"(v));
}

// ---- scratch ----
__device__ __align__(16) float g_W1t[34 * 128];
__device__ __align__(16) float g_W2t[128 * 256];
__device__ __align__(16) float g_W3t[256 * 128];
__device__ __align__(16) float g_W4t[128 * 16];
__device__ __align__(16) float g_h2[(size_t)R_ * E2_];
__device__ float g_sd[R_ * K_];
__device__ int   g_si[R_ * K_];
__device__ float g_psA [GA_ * E2_];
__device__ float g_pssA[GA_ * E2_];
__device__ float g_ps [B_ * SCH_ * E2_];
__device__ float g_pss[B_ * SCH_ * E2_];
__device__ float g_scale[B_ * E2_];
__device__ float g_shift[B_ * E2_];
__device__ int   g_bcnt;

// ---- kernel T: all four weight transposes ----
__global__ __launch_bounds__(256) void kT(const float* __restrict__ W1,
                                          const float* __restrict__ W2,
                                          const float* __restrict__ W3,
                                          const float* __restrict__ W4) {
  int t = blockIdx.x * blockDim.x + threadIdx.x;
  int stride = gridDim.x * blockDim.x;
  for (int o = t; o < 34 * 128; o += stride) { int co = o & 127, j = o >> 7; g_W1t[o] = W1[co * 34 + j]; }
  for (int o = t; o < 128 * 256; o += stride) { int co = o & 255, c = o >> 8; g_W2t[o] = W2[co * 128 + c]; }
  for (int o = t; o < 256 * 128; o += stride) { int co = o & 127, c = o >> 7; g_W3t[o] = W3[co * 256 + c]; }
  for (int o = t; o < 128 * 16;  o += stride) { int k  = o & 15,  c = o >> 4; g_W4t[o] = W4[k * 128 + c]; }
}

// ---- kernel A: top-16 + layers 1-2 + norm partials; fill interleaved in L2 ----
__global__ __launch_bounds__(256) void kA(const float* __restrict__ theta,
                                          const float* __restrict__ dist,
                                          const float* __restrict__ insf,
                                          const float* __restrict__ b1,
                                          const float* __restrict__ b2,
                                          float* __restrict__ out) {
  int blk = blockIdx.x;
  int r0 = blk * RPB_;
  int tid = threadIdx.x, wid = tid >> 5, lane = tid & 31;

  __shared__ int slots[RPB_][32][SLOT_];           // 8KB
  __shared__ ull cand[RPB_][CAP_];                 // 8KB
  __shared__ float sds[RPB_][K_];
  __shared__ int   sis[RPB_][K_];
  __shared__ float xs[RPB_][34];
  __shared__ __align__(16) float h1t[128][RPB_];   // 4KB
  __shared__ ull p2[RPB_][2][128];                 // 16KB, lane-consecutive

  // ---- filter pass 1: read-only streaming scan ----
  int r = r0 + wid;
  const float* drow = dist + (size_t)r * M_;
  const float4* drow4 = reinterpret_cast<const float4*>(drow);
  int ci = 0;
  #pragma unroll 4
  for (int it = 0; it < 16; it++) {
    int i4 = it * 32 + lane;
    float4 v = (i4 < M_ / 4) ? drow4[i4] : make_float4(1.f, 1.f, 1.f, 1.f);
    int base = i4 * 4;
    if (v.x < TAU_) { if (ci < SLOT_) slots[wid][lane][ci] = base + 0; ci++; }
    if (v.y < TAU_) { if (ci < SLOT_) slots[wid][lane][ci] = base + 1; ci++; }
    if (v.z < TAU_) { if (ci < SLOT_) slots[wid][lane][ci] = base + 2; ci++; }
    if (v.w < TAU_) { if (ci < SLOT_) slots[wid][lane][ci] = base + 3; ci++; }
  }
  unsigned om = __ballot_sync(0xffffffffu, ci > SLOT_);
  int pre = ci;
  #pragma unroll
  for (int d = 1; d < 32; d <<= 1) {
    int o = __shfl_up_sync(0xffffffffu, pre, d);
    if (lane >= d) pre += o;
  }
  int C = __shfl_sync(0xffffffffu, pre, 31);
  int p = pre - ci;

  if (om == 0 && C >= K_ && C <= CAP_) {
    // ---- compaction + rank-select ----
    for (int s = 0; s < ci; s++) {
      int idx = slots[wid][lane][s];
      float v = __ldg(&drow[idx]);
      cand[wid][p + s] = (((ull)__float_as_uint(v)) << 32) | (unsigned)idx;
    }
    __syncwarp();
    for (int i = lane; i < C; i += 32) {
      ull key = cand[wid][i];
      int rank = 0;
      for (int j = 0; j < C; j++) rank += (cand[wid][j] < key);
      if (rank < K_) {
        sds[wid][rank] = __uint_as_float((unsigned)(key >> 32));
        sis[wid][rank] = (int)(unsigned)(key & 0xffffffffu);
      }
    }
  } else {
    // ---- exact fallback (deterministic, rare) ----
    ull last = 0ULL;
    for (int k = 0; k < K_; k++) {
      ull m = ~0ULL;
      for (int i = lane; i < M_; i += 32) {
        ull c = (((ull)__float_as_uint(drow[i])) << 32) | (unsigned)i;
        if ((k == 0 || c > last) && c < m) m = c;
      }
      #pragma unroll
      for (int off = 16; off; off >>= 1) {
        ull o = __shfl_down_sync(0xffffffffu, m, off);
        m = (o < m) ? o : m;
      }
      m = __shfl_sync(0xffffffffu, m, 0);
      if (lane == 0) {
        sds[wid][k] = __uint_as_float((unsigned)(m >> 32));
        sis[wid][k] = (int)(unsigned)(m & 0xffffffffu);
      }
      last = m;
    }
  }
  __syncwarp();

  // ---- build x per row ----
  if (lane < K_) {
    float maxd = sds[wid][K_ - 1];
    float nd = sds[wid][lane] / maxd;
    xs[wid][lane] = nd;
    xs[wid][K_ + lane] = theta[(size_t)r * M_ + sis[wid][lane]];
    g_sd[r * K_ + lane] = nd;
    g_si[r * K_ + lane] = sis[wid][lane];
  }
  if (lane == 16) xs[wid][32] = insf[r];
  if (lane == 17) xs[wid][33] = insf[R_ + r];
  __syncthreads();

  // ---- layer 1: 34 -> 128, relu ----
  {
    int co = tid & 127, rg = (tid >> 7) * 4;
    float bb = b1[co];
    float a0 = bb, a1 = bb, a2 = bb, a3 = bb;
    #pragma unroll
    for (int j = 0; j < 34; j++) {
      float w = g_W1t[j * 128 + co];
      a0 = fmaf(xs[rg + 0][j], w, a0);
      a1 = fmaf(xs[rg + 1][j], w, a1);
      a2 = fmaf(xs[rg + 2][j], w, a2);
      a3 = fmaf(xs[rg + 3][j], w, a3);
    }
    h1t[co][rg + 0] = fmaxf(a0, 0.f);
    h1t[co][rg + 1] = fmaxf(a1, 0.f);
    h1t[co][rg + 2] = fmaxf(a2, 0.f);
    h1t[co][rg + 3] = fmaxf(a3, 0.f);
  }
  __syncthreads();

  // ---- layer 2: 128 -> 256 for 8 rows; PENALTY fill interleaved (1 STG/chunk) ----
  {
    int pr = tid & 127, seg = tid >> 7;
    int c0 = seg * 64;
    const ull* W2p = reinterpret_cast<const ull*>(g_W2t);
    float4* o4 = reinterpret_cast<float4*>(out + (size_t)r0 * M_);
    const float4 pen = make_float4(PENALTY_, PENALTY_, PENALTY_, PENALTY_);
    ull acc[RPB_];
    #pragma unroll
    for (int rr = 0; rr < RPB_; rr++) acc[rr] = 0ULL;
    #pragma unroll
    for (int chunk = 0; chunk < 16; chunk++) {
      #pragma unroll
      for (int cc4 = 0; cc4 < 4; cc4++) {
        int c = c0 + chunk * 4 + cc4;
        ull w = W2p[c * 128 + pr];
        float4 ha = *reinterpret_cast<const float4*>(&h1t[c][0]);
        float4 hb = *reinterpret_cast<const float4*>(&h1t[c][4]);
        acc[0] = fma2(packdup(ha.x), w, acc[0]);
        acc[1] = fma2(packdup(ha.y), w, acc[1]);
        acc[2] = fma2(packdup(ha.z), w, acc[2]);
        acc[3] = fma2(packdup(ha.w), w, acc[3]);
        acc[4] = fma2(packdup(hb.x), w, acc[4]);
        acc[5] = fma2(packdup(hb.y), w, acc[5]);
        acc[6] = fma2(packdup(hb.z), w, acc[6]);
        acc[7] = fma2(packdup(hb.w), w, acc[7]);
      }
      // one fill store per chunk: rides idle issue slots, drains in background
      int fi = chunk * 256 + tid;
      if (fi < RPB_ * M_ / 4) o4[fi] = pen;
    }
    #pragma unroll
    for (int rr = 0; rr < RPB_; rr++) p2[rr][seg][pr] = acc[rr];
  }
  __syncthreads();
  // ---- epilogue: bias+relu, store h2, norm partials ----
  if (tid < 128) {
    float2 bb = reinterpret_cast<const float2*>(b2)[tid];
    float s0 = 0.f, s1 = 0.f, q0 = 0.f, q1 = 0.f;
    #pragma unroll
    for (int rr = 0; rr < RPB_; rr++) {
      ull s = add2(p2[rr][0][tid], p2[rr][1][tid]);
      float sx, sy;
      unpack2(s, sx, sy);
      float2 o;
      o.x = fmaxf(sx + bb.x, 0.f);
      o.y = fmaxf(sy + bb.y, 0.f);
      reinterpret_cast<float2*>(g_h2)[(size_t)(r0 + rr) * 128 + tid] = o;
      s0 += o.x; q0 = fmaf(o.x, o.x, q0);
      s1 += o.y; q1 = fmaf(o.y, o.y, q1);
    }
    g_psA [blk * E2_ + 2 * tid + 0] = s0;
    g_psA [blk * E2_ + 2 * tid + 1] = s1;
    g_pssA[blk * E2_ + 2 * tid + 0] = q0;
    g_pssA[blk * E2_ + 2 * tid + 1] = q1;
  }
}

// ---- kernel B ----
__global__ __launch_bounds__(256) void kB(const float* __restrict__ gamma,
                                          const float* __restrict__ beta) {
  int blk = blockIdx.x;
  int b = blk >> 3, s = blk & 7;
  int t = threadIdx.x;
  int i0 = s * 32, i1 = min(i0 + 32, BPB_);
  float sum = 0.f, sq = 0.f;
  for (int i = i0; i < i1; i++) {
    int pb = b * BPB_ + i;
    sum += g_psA [pb * E2_ + t];
    sq  += g_pssA[pb * E2_ + t];
  }
  g_ps [(b * SCH_ + s) * E2_ + t] = sum;
  g_pss[(b * SCH_ + s) * E2_ + t] = sq;

  __threadfence();
  __shared__ int isLast;
  if (t == 0) isLast = (atomicAdd(&g_bcnt, 1) == B_ * SCH_ - 1) ? 1 : 0;
  __syncthreads();
  if (!isLast) return;
  if (t == 0) g_bcnt = 0;

  for (int bb = 0; bb < B_; bb++) {
    float sf = 0.f, ssf = 0.f;
    #pragma unroll
    for (int c2 = 0; c2 < SCH_; c2++) {
      sf  += g_ps [(bb * SCH_ + c2) * E2_ + t];
      ssf += g_pss[(bb * SCH_ + c2) * E2_ + t];
    }
    float mean = sf * (1.f / N_);
    float var  = ssf * (1.f / N_) - mean * mean;
    float inv  = rsqrtf(var + EPS_);
    float sc = inv * gamma[t];
    g_scale[bb * E2_ + t] = sc;
    g_shift[bb * E2_ + t] = beta[t] - mean * sc;
  }
}

// ---- kernel C: 8 rows/block; norm, layers 3-4, scatter (no fill) ----
__global__ __launch_bounds__(256, 6) void kC(const float* __restrict__ b3,
                                             const float* __restrict__ b4,
                                             float* __restrict__ out) {
  int r0 = blockIdx.x * RPB_;
  int tid = threadIdx.x;
  int b = r0 / N_;

  __shared__ __align__(16) float hn[E2_][RPB_];    // 8KB
  __shared__ ull p3[RPB_][4][64];                  // 16KB, lane-consecutive
  __shared__ __align__(16) float h3t[EMB_][RPB_];  // 4KB
  __shared__ float part[2][128];

  // ---- load h2 + instance-norm ----
  {
    float sc = g_scale[b * E2_ + tid];
    float sh = g_shift[b * E2_ + tid];
    #pragma unroll
    for (int rr = 0; rr < RPB_; rr++) {
      float v = g_h2[(size_t)(r0 + rr) * E2_ + tid];
      hn[tid][rr] = fmaf(v, sc, sh);
    }
  }
  __syncthreads();

  // ---- layer 3: 256 -> 128 for 8 rows ----
  {
    int pr = tid & 63, seg = tid >> 6;
    int c0 = seg * 64;
    const ull* W3p = reinterpret_cast<const ull*>(g_W3t);
    ull acc[RPB_];
    #pragma unroll
    for (int rr = 0; rr < RPB_; rr++) acc[rr] = 0ULL;
    #pragma unroll 8
    for (int cc = 0; cc < 64; cc++) {
      int c = c0 + cc;
      ull w = W3p[c * 64 + pr];
      float4 ha = *reinterpret_cast<const float4*>(&hn[c][0]);
      float4 hb = *reinterpret_cast<const float4*>(&hn[c][4]);
      acc[0] = fma2(packdup(ha.x), w, acc[0]);
      acc[1] = fma2(packdup(ha.y), w, acc[1]);
      acc[2] = fma2(packdup(ha.z), w, acc[2]);
      acc[3] = fma2(packdup(ha.w), w, acc[3]);
      acc[4] = fma2(packdup(hb.x), w, acc[4]);
      acc[5] = fma2(packdup(hb.y), w, acc[5]);
      acc[6] = fma2(packdup(hb.z), w, acc[6]);
      acc[7] = fma2(packdup(hb.w), w, acc[7]);
    }
    #pragma unroll
    for (int rr = 0; rr < RPB_; rr++) p3[rr][seg][pr] = acc[rr];
  }
  __syncthreads();
  // ---- combine -> h3t, all 256 threads (2 rows each) ----
  {
    int pr = tid & 63, g = tid >> 6;
    float2 bb = reinterpret_cast<const float2*>(b3)[pr];
    #pragma unroll
    for (int q = 0; q < 2; q++) {
      int rr = 2 * g + q;
      ull s = add2(add2(p3[rr][0][pr], p3[rr][1][pr]),
                   add2(p3[rr][2][pr], p3[rr][3][pr]));
      float sx, sy;
      unpack2(s, sx, sy);
      h3t[2 * pr + 0][rr] = fmaxf(sx + bb.x, 0.f);
      h3t[2 * pr + 1][rr] = fmaxf(sy + bb.y, 0.f);
    }
  }
  __syncthreads();

  // ---- layer 4: 128 -> 16 per row (2 c-segments of 64) ----
  {
    int rk = tid & 127, seg = tid >> 7;
    int row = rk >> 4, k = rk & 15;
    int c0 = seg * 64;
    float acc = 0.f;
    #pragma unroll 8
    for (int cc = 0; cc < 64; cc++) {
      int c = c0 + cc;
      acc = fmaf(h3t[c][row], g_W4t[c * 16 + k], acc);
    }
    part[seg][rk] = acc;
  }
  __syncthreads();

  // ---- combine, subtract sorted_dist, scatter ----
  if (tid < 128) {
    int row = tid >> 4, k = tid & 15;
    int r = r0 + row;
    float val = part[0][tid] + part[1][tid] + b4[k] - g_sd[r * K_ + k];
    int idx = g_si[r * K_ + k];
    out[(size_t)r * M_ + idx] = val;
  }
}

extern "C" void kernel_launch(void* const* d_in, const int* in_sizes, int n_in,
                              void* d_out, int out_size) {
  const float* theta = (const float*)d_in[0];
  const float* dist  = (const float*)d_in[1];
  const float* insf  = (const float*)d_in[2];
  const float* W1    = (const float*)d_in[3];
  const float* b1    = (const float*)d_in[4];
  const float* W2    = (const float*)d_in[5];
  const float* b2    = (const float*)d_in[6];
  const float* W3    = (const float*)d_in[7];
  const float* b3    = (const float*)d_in[8];
  const float* W4    = (const float*)d_in[9];
  const float* b4    = (const float*)d_in[10];
  const float* gamma = (const float*)d_in[11];
  const float* beta  = (const float*)d_in[12];
  float* out = (float*)d_out;

  kT<<<72, 256>>>(W1, W2, W3, W4);
  kA<<<GA_, 256>>>(theta, dist, insf, b1, b2, out);
  kB<<<B_ * SCH_, 256>>>(gamma, beta);
  kC<<<GA_, 256>>>(b3, b4, out);
}